// round 9
// baseline (speedup 1.0000x reference)
#include <cuda_runtime.h>
#include <cuda_bf16.h>

#define B_   64
#define T_   512
#define DIN  256
#define H_   1024
#define DOUT 256
#define NCTA 128
#define NT   256

constexpr int KT0 = 16;   // Wi0 k-groups
constexpr int KTH = 64;   // Wh0/Wi1/Wh1 k-groups
constexpr int PD  = 4;    // cp.async pipeline depth (stages)
constexpr int SLOT = 10 * 512;              // bytes per stage per warp
constexpr int WREG = PD * SLOT;             // 20480 B per warp
constexpr int DYNSM = 8 * WREG;             // 163840 B

constexpr size_t FSZ0 = (size_t)64 * 3 * KT0 * 64;
constexpr size_t FSZH = (size_t)64 * 3 * KTH * 64;
constexpr size_t FB0 = 0, FB1 = FSZ0, FB2 = FSZ0 + FSZH, FB3 = FSZ0 + 2 * FSZH;

__device__ uint4 g_wA[FSZ0 + 3 * FSZH];          // fragment-direct weights (hi/lo)
__device__ float g_h0f[2][B_ * H_], g_h1f[2][B_ * H_];
__device__ uint4 g_h0x[2][KTH * B_ * 4];         // frag-ordered h0 [kg][b][qq]
__device__ uint4 g_h1x[2][KTH * B_ * 4];
__device__ uint4 g_xx[(size_t)T_ * KT0 * B_ * 4];// frag-ordered x  [t][kg][b][qq]
__device__ float g_pL0[NCTA * 4096];             // partials [cta][qty4][j16][b64]
__device__ float g_pL1[NCTA * 4096];
__device__ volatile unsigned g_fL0[NCTA], g_fL1[NCTA];
__device__ unsigned g_bar, g_done;

__device__ __forceinline__ unsigned short bfbits(float v) {
    __nv_bfloat16 b = __float2bfloat16_rn(v);
    return *reinterpret_cast<unsigned short*>(&b);
}
__device__ __forceinline__ float bf2f(unsigned short u) {
    __nv_bfloat16 b = *reinterpret_cast<__nv_bfloat16*>(&u);
    return __bfloat162float(b);
}
__device__ __forceinline__ unsigned pk(float a, float b) {
    return (unsigned)bfbits(a) | ((unsigned)bfbits(b) << 16);
}
__device__ __forceinline__ float resid(float w) { return w - bf2f(bfbits(w)); }
__device__ __forceinline__ float sigf(float x) {
    return __fdividef(1.0f, 1.0f + __expf(-x));
}
__device__ __forceinline__ float tanh_(float x) {
    return __fdividef(2.0f, 1.0f + __expf(-2.0f * x)) - 1.0f;
}

__device__ __forceinline__ void mma16816(float (&d)[4], const uint4 a,
                                         unsigned b0, unsigned b1) {
    asm volatile(
        "mma.sync.aligned.m16n8k16.row.col.f32.bf16.bf16.f32 "
        "{%0,%1,%2,%3},{%4,%5,%6,%7},{%8,%9},{%0,%1,%2,%3};"
        : "+f"(d[0]), "+f"(d[1]), "+f"(d[2]), "+f"(d[3])
        : "r"(a.x), "r"(a.y), "r"(a.z), "r"(a.w), "r"(b0), "r"(b1));
}

__device__ __forceinline__ void cp16(unsigned sdst, const void* gsrc) {
    asm volatile("cp.async.cg.shared.global [%0], [%1], 16;"
                 :: "r"(sdst), "l"(gsrc));
}
__device__ __forceinline__ void cp_commit() {
    asm volatile("cp.async.commit_group;");
}
template<int N>
__device__ __forceinline__ void cp_wait() {
    asm volatile("cp.async.wait_group %0;" :: "n"(N));
}
__device__ __forceinline__ uint4 lds128(unsigned a) {
    uint4 r;
    asm volatile("ld.shared.v4.u32 {%0,%1,%2,%3}, [%4];"
                 : "=r"(r.x), "=r"(r.y), "=r"(r.z), "=r"(r.w) : "r"(a));
    return r;
}

__device__ __forceinline__ void grid_sync(unsigned gen) {
    __syncthreads();
    if (threadIdx.x == 0) {
        __threadfence();
        atomicAdd(&g_bar, 1u);
        while (*((volatile unsigned*)&g_bar) < gen * NCTA) { }
        __threadfence();
    }
    __syncthreads();
}

// Pipelined GEMM slice: per-warp cp.async ring (depth PD) feeding the merged
// split-bf16 MMA block (3 gates x 4 n8 x fp32 accum).
template<int KT, int CNT>
__device__ __forceinline__ void mainloop_pipe(
    const uint4* __restrict__ fA,   // + jt*3*KT*64 + lane
    const uint4* __restrict__ bx,   // + nsub*128 + (lane>>2)*4 + (lane&3)
    int kgs, unsigned sbase,        // smem base for this warp (+lane*16)
    float (&aR)[4][4], float (&aZ)[4][4], float (&aN)[4][4])
{
    const uint4* a0 = fA + (size_t)kgs * 64;
    const uint4* bp = bx + (size_t)kgs * 256;

    auto issue = [&](int idx) {
        unsigned s = sbase + (unsigned)((idx & (PD - 1)) * SLOT);
        const uint4* aa = a0 + (size_t)idx * 64;
        const uint4* bb = bp + (size_t)idx * 256;
        cp16(s + 0 * 512, aa);
        cp16(s + 1 * 512, aa + 32);
        cp16(s + 2 * 512, aa + KT * 64);
        cp16(s + 3 * 512, aa + KT * 64 + 32);
        cp16(s + 4 * 512, aa + 2 * KT * 64);
        cp16(s + 5 * 512, aa + 2 * KT * 64 + 32);
        cp16(s + 6 * 512, bb);
        cp16(s + 7 * 512, bb + 32);
        cp16(s + 8 * 512, bb + 64);
        cp16(s + 9 * 512, bb + 96);
        cp_commit();
    };

#pragma unroll
    for (int i = 0; i < (CNT < PD ? CNT : PD); ++i) issue(i);

#pragma unroll
    for (int k = 0; k < CNT; ++k) {
        const int rem = CNT - 1 - k;      // groups that may stay pending
        if (rem >= 3) cp_wait<3>();
        else if (rem == 2) cp_wait<2>();
        else if (rem == 1) cp_wait<1>();
        else cp_wait<0>();

        unsigned s = sbase + (unsigned)((k & (PD - 1)) * SLOT);
        uint4 Ah0 = lds128(s + 0 * 512);
        uint4 Al0 = lds128(s + 1 * 512);
        uint4 Ah1 = lds128(s + 2 * 512);
        uint4 Al1 = lds128(s + 3 * 512);
        uint4 Ah2 = lds128(s + 4 * 512);
        uint4 Al2 = lds128(s + 5 * 512);
        uint4 v[4];
#pragma unroll
        for (int i = 0; i < 4; ++i) v[i] = lds128(s + (6 + i) * 512);

        if (k + PD < CNT) issue(k + PD);

#pragma unroll
        for (int i = 0; i < 4; ++i) {
            mma16816(aR[i], Ah0, v[i].x, v[i].y);
            mma16816(aZ[i], Ah1, v[i].x, v[i].y);
            mma16816(aN[i], Ah2, v[i].x, v[i].y);
            mma16816(aR[i], Ah0, v[i].z, v[i].w);
            mma16816(aZ[i], Ah1, v[i].z, v[i].w);
            mma16816(aN[i], Ah2, v[i].z, v[i].w);
            mma16816(aR[i], Al0, v[i].x, v[i].y);
            mma16816(aZ[i], Al1, v[i].x, v[i].y);
            mma16816(aN[i], Al2, v[i].x, v[i].y);
        }
    }
}

// ksub-reduce via SMEM + publish CTA partial [qty][j16][b64] to global.
#define REDUCE_PUBLISH(AR, AZ, ANI, ANH, POUT)                                 \
    do {                                                                       \
        if (ksub) {                                                           \
            float* dst = rbuf + (((ksub - 1) * 2 + nsub) * 64) * 32 + lane;   \
            _Pragma("unroll")                                                 \
            for (int i = 0; i < 16; ++i) {                                    \
                dst[(0 * 16 + i) * 32] = AR[i >> 2][i & 3];                   \
                dst[(1 * 16 + i) * 32] = AZ[i >> 2][i & 3];                   \
                dst[(2 * 16 + i) * 32] = ANI[i >> 2][i & 3];                  \
                dst[(3 * 16 + i) * 32] = ANH[i >> 2][i & 3];                  \
            }                                                                 \
        }                                                                     \
        __syncthreads();                                                      \
        if (ksub == 0) {                                                      \
            _Pragma("unroll")                                                 \
            for (int q = 0; q < 4; ++q) {                                     \
                _Pragma("unroll")                                             \
                for (int i = 0; i < 16; ++i) {                                \
                    float v = (q == 0 ? AR[i >> 2][i & 3]                     \
                             : q == 1 ? AZ[i >> 2][i & 3]                     \
                             : q == 2 ? ANI[i >> 2][i & 3]                    \
                                      : ANH[i >> 2][i & 3]);                  \
                    _Pragma("unroll")                                         \
                    for (int w = 0; w < 3; ++w)                               \
                        v += rbuf[((w * 2 + nsub) * 64 + q * 16 + i) * 32 + lane]; \
                    int jl = (lane >> 2) + 8 * ((i & 3) >> 1);                \
                    int b  = nsub * 32 + (i >> 2) * 8 + 2 * (lane & 3) + (i & 1); \
                    (POUT)[q * 1024 + jl * 64 + b] = v;                       \
                }                                                             \
            }                                                                 \
        }                                                                     \
        __syncthreads();                                                      \
    } while (0)

// Gate pass: this CTA gates local j rows [8*ks, 8*ks+8) for all 64 b.
__device__ __forceinline__ void gatepass(
    const float* __restrict__ pOwn, const float* __restrict__ pPar,
    const float* bsv,
    const float* __restrict__ hpf, float* __restrict__ hnf,
    uint4* __restrict__ hx,
    int jt, int ks, int tid)
{
    const int b = tid & 63, jl2 = tid >> 6;
#pragma unroll
    for (int jj = 0; jj < 2; ++jj) {
        int jl = 8 * ks + jl2 * 2 + jj;
        int j  = jt * 16 + jl;
        int o  = jl * 64 + b;
        float r  = pOwn[o]        + pPar[o];
        float z  = pOwn[1024 + o] + pPar[1024 + o];
        float ni = pOwn[2048 + o] + pPar[2048 + o];
        float nh = pOwn[3072 + o] + pPar[3072 + o];
        r = sigf(r + bsv[jj * 4 + 0]);
        z = sigf(z + bsv[jj * 4 + 1]);
        float n = tanh_(ni + bsv[jj * 4 + 2] + r * (nh + bsv[jj * 4 + 3]));
        float hp = hpf[b * H_ + j];
        float h  = n + z * (hp - n);
        hnf[b * H_ + j] = h;
        unsigned short uh = bfbits(h);
        unsigned short ul = bfbits(h - bf2f(uh));
        int kg = j >> 4, pw = (j & 15) >> 1, qq = pw & 3, sl = pw >> 2;
        char* base = (char*)(hx + (size_t)(kg * 64 + b) * 4 + qq);
        *(unsigned short*)(base + sl * 4 + (j & 1) * 2)     = uh;
        *(unsigned short*)(base + 8 + sl * 4 + (j & 1) * 2) = ul;
    }
}

__global__ void __launch_bounds__(NT, 1) gru_tc3(
    const float* __restrict__ x,
    const float* __restrict__ Wi0, const float* __restrict__ Wh0,
    const float* __restrict__ bi0, const float* __restrict__ bh0,
    const float* __restrict__ Wi1, const float* __restrict__ Wh1,
    const float* __restrict__ bi1, const float* __restrict__ bh1,
    const float* __restrict__ Wo,  const float* __restrict__ bo,
    float* __restrict__ out)
{
    __shared__ float rbuf[3 * 2 * 64 * 32];   // 48 KB ksub-reduce buffer
    extern __shared__ __align__(16) char dynsm[];

    const int tid  = threadIdx.x, lane = tid & 31, warp = tid >> 5;
    const int cta  = blockIdx.x;
    const int jt   = cta >> 1;       // j-tile (16 rows)
    const int ks   = cta & 1;        // k-half
    const int nsub = warp & 1;       // batch half (32)
    const int ksub = warp >> 1;      // k-quarter of the half

    const unsigned smb = (unsigned)__cvta_generic_to_shared(dynsm);
    const unsigned sbase = smb + (unsigned)warp * WREG + (unsigned)lane * 16;

    // ---- prep: x -> fragment-ordered split-bf16 ----
    {
        unsigned* xw = (unsigned*)g_xx;
        const int XW = T_ * KT0 * B_ * 16;
        for (int w = cta * NT + tid; w < XW; w += NCTA * NT) {
            int wi = w & 3, qq = (w >> 2) & 3, b = (w >> 4) & 63;
            int kg = (w >> 10) & 15, t = w >> 14;
            int pw = (wi & 1) ? qq + 4 : qq;
            int k  = kg * 16 + pw * 2;
            float v0 = x[((size_t)b * T_ + t) * DIN + k];
            float v1 = x[((size_t)b * T_ + t) * DIN + k + 1];
            xw[w] = (wi < 2) ? pk(v0, v1) : pk(resid(v0), resid(v1));
        }
    }
    // ---- zero initial state (buffer 1 is read first) ----
    {
        unsigned* z0 = (unsigned*)g_h0x[1];
        unsigned* z1 = (unsigned*)g_h1x[1];
        for (int i = cta * NT + tid; i < KTH * B_ * 16; i += NCTA * NT) {
            z0[i] = 0u; z1[i] = 0u;
        }
        for (int i = cta * NT + tid; i < B_ * H_; i += NCTA * NT) {
            g_h0f[1][i] = 0.f; g_h1f[1][i] = 0.f;
        }
    }
    // ---- weights -> fragment-direct split-bf16 table ----
    {
        const float* Wp[4] = { Wi0, Wh0, Wi1, Wh1 };
        const int    Kp[4] = { DIN, H_, H_, H_ };
        const size_t Fp[4] = { FB0, FB1, FB2, FB3 };
        for (int p = 0; p < 4; ++p) {
            const int K = Kp[p], KT = K / 16;
            const float* W = Wp[p];
            const int total = 64 * 3 * KT * 32;
            for (int i = cta * NT + tid; i < total; i += NCTA * NT) {
                int l = i & 31, item = i >> 5;
                int kg = item % KT, g = (item / KT) % 3, jtt = item / (KT * 3);
                int m = l >> 2, kb = 2 * (l & 3);
                const float* r0 = W + (size_t)(g * H_ + jtt * 16 + m) * K + kg * 16 + kb;
                const float* r1 = r0 + 8 * (size_t)K;
                float w00 = r0[0], w01 = r0[1], w02 = r0[8], w03 = r0[9];
                float w10 = r1[0], w11 = r1[1], w12 = r1[8], w13 = r1[9];
                uint4 hv, lv;
                hv.x = pk(w00, w01); hv.y = pk(w10, w11);
                hv.z = pk(w02, w03); hv.w = pk(w12, w13);
                lv.x = pk(resid(w00), resid(w01)); lv.y = pk(resid(w10), resid(w11));
                lv.z = pk(resid(w02), resid(w03)); lv.w = pk(resid(w12), resid(w13));
                size_t base = Fp[p] + ((size_t)(jtt * 3 + g) * KT + kg) * 64;
                g_wA[base + l] = hv;
                g_wA[base + 32 + l] = lv;
            }
        }
    }
    // ---- per-thread gate-pass biases ----
    float bs0v[8], bs1v[8];
    {
        const int jl2 = tid >> 6;
#pragma unroll
        for (int jj = 0; jj < 2; ++jj) {
            int j = jt * 16 + 8 * ks + jl2 * 2 + jj;
            bs0v[jj * 4 + 0] = bi0[j] + bh0[j];
            bs0v[jj * 4 + 1] = bi0[H_ + j] + bh0[H_ + j];
            bs0v[jj * 4 + 2] = bi0[2 * H_ + j];
            bs0v[jj * 4 + 3] = bh0[2 * H_ + j];
            bs1v[jj * 4 + 0] = bi1[j] + bh1[j];
            bs1v[jj * 4 + 1] = bi1[H_ + j] + bh1[H_ + j];
            bs1v[jj * 4 + 2] = bi1[2 * H_ + j];
            bs1v[jj * 4 + 3] = bh1[2 * H_ + j];
        }
    }

    const uint4* fWi0 = g_wA + FB0 + (size_t)jt * 3 * KT0 * 64 + lane;
    const uint4* fWh0 = g_wA + FB1 + (size_t)jt * 3 * KTH * 64 + lane;
    const uint4* fWi1 = g_wA + FB2 + (size_t)jt * 3 * KTH * 64 + lane;
    const uint4* fWh1 = g_wA + FB3 + (size_t)jt * 3 * KTH * 64 + lane;
    const unsigned boff = nsub * 128 + (lane >> 2) * 4 + (lane & 3);
    const int kgs0 = ks * 8  + ksub * 2;   // Wi0 (KT=16): 2 kg per warp
    const int kgsH = ks * 32 + ksub * 8;   // KT=64 GEMMs: 8 kg per warp

    float* pOwn0 = g_pL0 + cta * 4096;
    float* pOwn1 = g_pL1 + cta * 4096;
    const float* pPar0 = g_pL0 + (cta ^ 1) * 4096;
    const float* pPar1 = g_pL1 + (cta ^ 1) * 4096;

    unsigned gen = 0;
    grid_sync(++gen);   // prep visible

    for (int p = 0; p <= T_; ++p) {
        // ---- layer0(t=p) partial: Wi0 x x(p) + Wh0 x h0(p-1) ----
        if (p < T_) {
            float aR[4][4] = {}, aZ[4][4] = {}, aNi[4][4] = {}, aNh[4][4] = {};
            mainloop_pipe<KT0, 2>(fWi0, g_xx + (size_t)p * 4096 + boff, kgs0,
                                  sbase, aR, aZ, aNi);
            mainloop_pipe<KTH, 8>(fWh0, g_h0x[(p + 1) & 1] + boff, kgsH,
                                  sbase, aR, aZ, aNh);
            REDUCE_PUBLISH(aR, aZ, aNi, aNh, pOwn0);
        }
        __syncthreads();
        if (tid == 0 && p < T_) { __threadfence(); g_fL0[cta] = p + 1; }
        // ---- layer1(t=p-1) partial: Wi1 x h0(p-1) + Wh1 x h1(p-2) ----
        if (p > 0) {
            float aR[4][4] = {}, aZ[4][4] = {}, aNi[4][4] = {}, aNh[4][4] = {};
            mainloop_pipe<KTH, 8>(fWi1, g_h0x[(p + 1) & 1] + boff, kgsH,
                                  sbase, aR, aZ, aNi);
            mainloop_pipe<KTH, 8>(fWh1, g_h1x[p & 1] + boff, kgsH,
                                  sbase, aR, aZ, aNh);
            REDUCE_PUBLISH(aR, aZ, aNi, aNh, pOwn1);
        }
        __syncthreads();
        if (tid == 0) {
            if (p > 0) { __threadfence(); g_fL1[cta] = p; }
            if (p < T_) while (g_fL0[cta ^ 1] < (unsigned)(p + 1)) { }
            if (p > 0)  while (g_fL1[cta ^ 1] < (unsigned)p) { }
            __threadfence();
        }
        __syncthreads();
        // ---- gate passes ----
        if (p < T_)
            gatepass(pOwn0, pPar0, bs0v, g_h0f[(p + 1) & 1], g_h0f[p & 1],
                     g_h0x[p & 1], jt, ks, tid);
        if (p > 0)
            gatepass(pOwn1, pPar1, bs1v, g_h1f[p & 1], g_h1f[(p + 1) & 1],
                     g_h1x[(p + 1) & 1], jt, ks, tid);
        grid_sync(++gen);
    }

    // ---- output projection: h1(511) is fp32 in g_h1f[1] ----
    if (tid < 128) {
        const int o = cta * 2 + (tid >> 6);
        const int b = tid & 63;
        const float* w  = Wo + (size_t)o * H_;
        const float* hv = g_h1f[1] + (size_t)b * H_;
        float acc = 0.f;
#pragma unroll 4
        for (int k = 0; k < H_; k += 4) {
            float4 wv = *reinterpret_cast<const float4*>(w + k);
            float4 h4 = *reinterpret_cast<const float4*>(hv + k);
            acc += wv.x * h4.x + wv.y * h4.y + wv.z * h4.z + wv.w * h4.w;
        }
        out[(size_t)b * DOUT + o] = acc + bo[o];
    }

    // ---- reset persistent counters/flags for the next replay ----
    __syncthreads();
    if (tid == 0) {
        unsigned old = atomicAdd(&g_done, 1u);
        if (old == NCTA - 1u) {
            for (int i = 0; i < NCTA; ++i) { g_fL0[i] = 0u; g_fL1[i] = 0u; }
            g_bar = 0u;
            g_done = 0u;
            __threadfence();
        }
    }
}

extern "C" void kernel_launch(void* const* d_in, const int* in_sizes, int n_in,
                              void* d_out, int out_size)
{
    cudaFuncSetAttribute(gru_tc3, cudaFuncAttributeMaxDynamicSharedMemorySize,
                         DYNSM);
    gru_tc3<<<NCTA, NT, DYNSM>>>(
        (const float*)d_in[0], (const float*)d_in[1], (const float*)d_in[2],
        (const float*)d_in[3], (const float*)d_in[4], (const float*)d_in[5],
        (const float*)d_in[6], (const float*)d_in[7], (const float*)d_in[8],
        (const float*)d_in[9], (const float*)d_in[10], (float*)d_out);
}

// round 10
// speedup vs baseline: 1.0216x; 1.0216x over previous
#include <cuda_runtime.h>
#include <cuda_bf16.h>

#define B_   64
#define T_   512
#define DIN  256
#define H_   1024
#define DOUT 256
#define NCTA 128
#define NT   256

constexpr int KT0 = 16;
constexpr int KTH = 64;
constexpr int PD  = 4;
constexpr int SLOT = 10 * 512;
constexpr int WREG = PD * SLOT;
constexpr int DYNSM = 8 * WREG;

constexpr size_t FSZ0 = (size_t)64 * 3 * KT0 * 64;
constexpr size_t FSZH = (size_t)64 * 3 * KTH * 64;
constexpr size_t FB0 = 0, FB1 = FSZ0, FB2 = FSZ0 + FSZH, FB3 = FSZ0 + 2 * FSZH;

__device__ uint4 g_wA[FSZ0 + 3 * FSZH];
__device__ float g_h0f[2][B_ * H_], g_h1f[2][B_ * H_];
__device__ uint4 g_h0x[2][KTH * B_ * 4];
__device__ uint4 g_h1x[2][KTH * B_ * 4];
__device__ uint4 g_xx[(size_t)T_ * KT0 * B_ * 4];
__device__ float g_pL0[NCTA * 4096];
__device__ float g_pL1[NCTA * 4096];
__device__ volatile unsigned g_fL0[NCTA], g_fL1[NCTA];
__device__ unsigned g_bar, g_done;

__device__ __forceinline__ unsigned short bfbits(float v) {
    __nv_bfloat16 b = __float2bfloat16_rn(v);
    return *reinterpret_cast<unsigned short*>(&b);
}
__device__ __forceinline__ float bf2f(unsigned short u) {
    __nv_bfloat16 b = *reinterpret_cast<__nv_bfloat16*>(&u);
    return __bfloat162float(b);
}
__device__ __forceinline__ unsigned pk(float a, float b) {
    return (unsigned)bfbits(a) | ((unsigned)bfbits(b) << 16);
}
__device__ __forceinline__ float resid(float w) { return w - bf2f(bfbits(w)); }
__device__ __forceinline__ float sigf(float x) {
    return __fdividef(1.0f, 1.0f + __expf(-x));
}
__device__ __forceinline__ float tanh_(float x) {
    return __fdividef(2.0f, 1.0f + __expf(-2.0f * x)) - 1.0f;
}

__device__ __forceinline__ void mma16816(float (&d)[4], const uint4 a,
                                         unsigned b0, unsigned b1) {
    asm volatile(
        "mma.sync.aligned.m16n8k16.row.col.f32.bf16.bf16.f32 "
        "{%0,%1,%2,%3},{%4,%5,%6,%7},{%8,%9},{%0,%1,%2,%3};"
        : "+f"(d[0]), "+f"(d[1]), "+f"(d[2]), "+f"(d[3])
        : "r"(a.x), "r"(a.y), "r"(a.z), "r"(a.w), "r"(b0), "r"(b1));
}
__device__ __forceinline__ void cp16(unsigned sdst, const void* gsrc) {
    asm volatile("cp.async.cg.shared.global [%0], [%1], 16;"
                 :: "r"(sdst), "l"(gsrc));
}
__device__ __forceinline__ void cp_commit() {
    asm volatile("cp.async.commit_group;");
}
template<int N>
__device__ __forceinline__ void cp_wait() {
    asm volatile("cp.async.wait_group %0;" :: "n"(N));
}
__device__ __forceinline__ uint4 lds128(unsigned a) {
    uint4 r;
    asm volatile("ld.shared.v4.u32 {%0,%1,%2,%3}, [%4];"
                 : "=r"(r.x), "=r"(r.y), "=r"(r.z), "=r"(r.w) : "r"(a));
    return r;
}
__device__ __forceinline__ void grid_sync(unsigned gen) {
    __syncthreads();
    if (threadIdx.x == 0) {
        __threadfence();
        atomicAdd(&g_bar, 1u);
        while (*((volatile unsigned*)&g_bar) < gen * NCTA) { }
        __threadfence();
    }
    __syncthreads();
}

// 3 rounds x 12 independent MMAs: accumulator reuse distance 12 (was 3).
__device__ __forceinline__ void mma_block(
    const uint4 Ah0, const uint4 Ah1, const uint4 Ah2,
    const uint4 Al0, const uint4 Al1, const uint4 Al2,
    const uint4 (&v)[4],
    float (&aR)[4][4], float (&aZ)[4][4], float (&aN)[4][4])
{
#pragma unroll
    for (int i = 0; i < 4; ++i) {
        mma16816(aR[i], Ah0, v[i].x, v[i].y);
        mma16816(aZ[i], Ah1, v[i].x, v[i].y);
        mma16816(aN[i], Ah2, v[i].x, v[i].y);
    }
#pragma unroll
    for (int i = 0; i < 4; ++i) {
        mma16816(aR[i], Ah0, v[i].z, v[i].w);
        mma16816(aZ[i], Ah1, v[i].z, v[i].w);
        mma16816(aN[i], Ah2, v[i].z, v[i].w);
    }
#pragma unroll
    for (int i = 0; i < 4; ++i) {
        mma16816(aR[i], Al0, v[i].x, v[i].y);
        mma16816(aZ[i], Al1, v[i].x, v[i].y);
        mma16816(aN[i], Al2, v[i].x, v[i].y);
    }
}

// Unified two-segment pipeline: seg0 (CNT0 kg, N-gate -> aN0), seg1 (CNT1 kg,
// N-gate -> aN1). One prologue bubble per layer instead of two.
template<int KTA, int CNT0, int KTB, int CNT1>
__device__ __forceinline__ void mainloop2(
    const uint4* __restrict__ fA0, const uint4* __restrict__ bx0, int kgs0,
    const uint4* __restrict__ fA1, const uint4* __restrict__ bx1, int kgs1,
    unsigned sbase,
    float (&aR)[4][4], float (&aZ)[4][4],
    float (&aN0)[4][4], float (&aN1)[4][4])
{
    constexpr int CNT = CNT0 + CNT1;
    const uint4* a0 = fA0 + (size_t)kgs0 * 64;
    const uint4* b0p = bx0 + (size_t)kgs0 * 256;
    const uint4* a1 = fA1 + (size_t)kgs1 * 64;
    const uint4* b1p = bx1 + (size_t)kgs1 * 256;

    auto issue = [&](int idx) {
        unsigned s = sbase + (unsigned)((idx & (PD - 1)) * SLOT);
        const bool s0 = idx < CNT0;
        const uint4* aa = s0 ? a0 + (size_t)idx * 64
                             : a1 + (size_t)(idx - CNT0) * 64;
        const uint4* bb = s0 ? b0p + (size_t)idx * 256
                             : b1p + (size_t)(idx - CNT0) * 256;
        const int kt = s0 ? KTA : KTB;
        cp16(s + 0 * 512, aa);
        cp16(s + 1 * 512, aa + 32);
        cp16(s + 2 * 512, aa + kt * 64);
        cp16(s + 3 * 512, aa + kt * 64 + 32);
        cp16(s + 4 * 512, aa + 2 * kt * 64);
        cp16(s + 5 * 512, aa + 2 * kt * 64 + 32);
        cp16(s + 6 * 512, bb);
        cp16(s + 7 * 512, bb + 32);
        cp16(s + 8 * 512, bb + 64);
        cp16(s + 9 * 512, bb + 96);
        cp_commit();
    };

#pragma unroll
    for (int i = 0; i < (CNT < PD ? CNT : PD); ++i) issue(i);

#pragma unroll
    for (int k = 0; k < CNT; ++k) {
        const int rem = CNT - 1 - k;
        if (rem >= 3) cp_wait<3>();
        else if (rem == 2) cp_wait<2>();
        else if (rem == 1) cp_wait<1>();
        else cp_wait<0>();

        unsigned s = sbase + (unsigned)((k & (PD - 1)) * SLOT);
        uint4 Ah0 = lds128(s + 0 * 512);
        uint4 Al0 = lds128(s + 1 * 512);
        uint4 Ah1 = lds128(s + 2 * 512);
        uint4 Al1 = lds128(s + 3 * 512);
        uint4 Ah2 = lds128(s + 4 * 512);
        uint4 Al2 = lds128(s + 5 * 512);
        uint4 v[4];
#pragma unroll
        for (int i = 0; i < 4; ++i) v[i] = lds128(s + (6 + i) * 512);

        if (k + PD < CNT) issue(k + PD);

        if (k < CNT0)
            mma_block(Ah0, Ah1, Ah2, Al0, Al1, Al2, v, aR, aZ, aN0);
        else
            mma_block(Ah0, Ah1, Ah2, Al0, Al1, Al2, v, aR, aZ, aN1);
    }
}

#define REDUCE_PUBLISH(AR, AZ, ANI, ANH, POUT)                                 \
    do {                                                                       \
        if (ksub) {                                                           \
            float* dst = rbuf + (((ksub - 1) * 2 + nsub) * 64) * 32 + lane;   \
            _Pragma("unroll")                                                 \
            for (int i = 0; i < 16; ++i) {                                    \
                dst[(0 * 16 + i) * 32] = AR[i >> 2][i & 3];                   \
                dst[(1 * 16 + i) * 32] = AZ[i >> 2][i & 3];                   \
                dst[(2 * 16 + i) * 32] = ANI[i >> 2][i & 3];                  \
                dst[(3 * 16 + i) * 32] = ANH[i >> 2][i & 3];                  \
            }                                                                 \
        }                                                                     \
        __syncthreads();                                                      \
        if (ksub == 0) {                                                      \
            _Pragma("unroll")                                                 \
            for (int q = 0; q < 4; ++q) {                                     \
                _Pragma("unroll")                                             \
                for (int i = 0; i < 16; ++i) {                                \
                    float v = (q == 0 ? AR[i >> 2][i & 3]                     \
                             : q == 1 ? AZ[i >> 2][i & 3]                     \
                             : q == 2 ? ANI[i >> 2][i & 3]                    \
                                      : ANH[i >> 2][i & 3]);                  \
                    _Pragma("unroll")                                         \
                    for (int w = 0; w < 3; ++w)                               \
                        v += rbuf[((w * 2 + nsub) * 64 + q * 16 + i) * 32 + lane]; \
                    int jl = (lane >> 2) + 8 * ((i & 3) >> 1);                \
                    int b  = nsub * 32 + (i >> 2) * 8 + 2 * (lane & 3) + (i & 1); \
                    (POUT)[q * 1024 + jl * 64 + b] = v;                       \
                }                                                             \
            }                                                                 \
        }                                                                     \
        __syncthreads();                                                      \
    } while (0)

__device__ __forceinline__ void gatepass(
    const float* __restrict__ pOwn, const float* __restrict__ pPar,
    const float* bsv,
    const float* __restrict__ hpf, float* __restrict__ hnf,
    uint4* __restrict__ hx,
    int jt, int ks, int tid)
{
    const int b = tid & 63, jl2 = tid >> 6;
#pragma unroll
    for (int jj = 0; jj < 2; ++jj) {
        int jl = 8 * ks + jl2 * 2 + jj;
        int j  = jt * 16 + jl;
        int o  = jl * 64 + b;
        float r  = pOwn[o]        + pPar[o];
        float z  = pOwn[1024 + o] + pPar[1024 + o];
        float ni = pOwn[2048 + o] + pPar[2048 + o];
        float nh = pOwn[3072 + o] + pPar[3072 + o];
        r = sigf(r + bsv[jj * 4 + 0]);
        z = sigf(z + bsv[jj * 4 + 1]);
        float n = tanh_(ni + bsv[jj * 4 + 2] + r * (nh + bsv[jj * 4 + 3]));
        float hp = hpf[b * H_ + j];
        float h  = n + z * (hp - n);
        hnf[b * H_ + j] = h;
        unsigned short uh = bfbits(h);
        unsigned short ul = bfbits(h - bf2f(uh));
        int kg = j >> 4, pw = (j & 15) >> 1, qq = pw & 3, sl = pw >> 2;
        char* base = (char*)(hx + (size_t)(kg * 64 + b) * 4 + qq);
        *(unsigned short*)(base + sl * 4 + (j & 1) * 2)     = uh;
        *(unsigned short*)(base + 8 + sl * 4 + (j & 1) * 2) = ul;
    }
}

__global__ void __launch_bounds__(NT, 1) gru_tc4(
    const float* __restrict__ x,
    const float* __restrict__ Wi0, const float* __restrict__ Wh0,
    const float* __restrict__ bi0, const float* __restrict__ bh0,
    const float* __restrict__ Wi1, const float* __restrict__ Wh1,
    const float* __restrict__ bi1, const float* __restrict__ bh1,
    const float* __restrict__ Wo,  const float* __restrict__ bo,
    float* __restrict__ out)
{
    __shared__ float rbuf[3 * 2 * 64 * 32];
    extern __shared__ __align__(16) char dynsm[];

    const int tid  = threadIdx.x, lane = tid & 31, warp = tid >> 5;
    const int cta  = blockIdx.x;
    const int jt   = cta >> 1;
    const int ks   = cta & 1;
    const int nsub = warp & 1;
    const int ksub = warp >> 1;

    const unsigned smb = (unsigned)__cvta_generic_to_shared(dynsm);
    const unsigned sbase = smb + (unsigned)warp * WREG + (unsigned)lane * 16;

    {   // x -> fragment-ordered split-bf16
        unsigned* xw = (unsigned*)g_xx;
        const int XW = T_ * KT0 * B_ * 16;
        for (int w = cta * NT + tid; w < XW; w += NCTA * NT) {
            int wi = w & 3, qq = (w >> 2) & 3, b = (w >> 4) & 63;
            int kg = (w >> 10) & 15, t = w >> 14;
            int pw = (wi & 1) ? qq + 4 : qq;
            int k  = kg * 16 + pw * 2;
            float v0 = x[((size_t)b * T_ + t) * DIN + k];
            float v1 = x[((size_t)b * T_ + t) * DIN + k + 1];
            xw[w] = (wi < 2) ? pk(v0, v1) : pk(resid(v0), resid(v1));
        }
    }
    {   // zero initial state
        unsigned* z0 = (unsigned*)g_h0x[1];
        unsigned* z1 = (unsigned*)g_h1x[1];
        for (int i = cta * NT + tid; i < KTH * B_ * 16; i += NCTA * NT) {
            z0[i] = 0u; z1[i] = 0u;
        }
        for (int i = cta * NT + tid; i < B_ * H_; i += NCTA * NT) {
            g_h0f[1][i] = 0.f; g_h1f[1][i] = 0.f;
        }
    }
    {   // weights -> fragment-direct split-bf16 table
        const float* Wp[4] = { Wi0, Wh0, Wi1, Wh1 };
        const int    Kp[4] = { DIN, H_, H_, H_ };
        const size_t Fp[4] = { FB0, FB1, FB2, FB3 };
        for (int p = 0; p < 4; ++p) {
            const int K = Kp[p], KT = K / 16;
            const float* W = Wp[p];
            const int total = 64 * 3 * KT * 32;
            for (int i = cta * NT + tid; i < total; i += NCTA * NT) {
                int l = i & 31, item = i >> 5;
                int kg = item % KT, g = (item / KT) % 3, jtt = item / (KT * 3);
                int m = l >> 2, kb = 2 * (l & 3);
                const float* r0 = W + (size_t)(g * H_ + jtt * 16 + m) * K + kg * 16 + kb;
                const float* r1 = r0 + 8 * (size_t)K;
                float w00 = r0[0], w01 = r0[1], w02 = r0[8], w03 = r0[9];
                float w10 = r1[0], w11 = r1[1], w12 = r1[8], w13 = r1[9];
                uint4 hv, lv;
                hv.x = pk(w00, w01); hv.y = pk(w10, w11);
                hv.z = pk(w02, w03); hv.w = pk(w12, w13);
                lv.x = pk(resid(w00), resid(w01)); lv.y = pk(resid(w10), resid(w11));
                lv.z = pk(resid(w02), resid(w03)); lv.w = pk(resid(w12), resid(w13));
                size_t base = Fp[p] + ((size_t)(jtt * 3 + g) * KT + kg) * 64;
                g_wA[base + l] = hv;
                g_wA[base + 32 + l] = lv;
            }
        }
    }
    float bs0v[8], bs1v[8];
    {
        const int jl2 = tid >> 6;
#pragma unroll
        for (int jj = 0; jj < 2; ++jj) {
            int j = jt * 16 + 8 * ks + jl2 * 2 + jj;
            bs0v[jj * 4 + 0] = bi0[j] + bh0[j];
            bs0v[jj * 4 + 1] = bi0[H_ + j] + bh0[H_ + j];
            bs0v[jj * 4 + 2] = bi0[2 * H_ + j];
            bs0v[jj * 4 + 3] = bh0[2 * H_ + j];
            bs1v[jj * 4 + 0] = bi1[j] + bh1[j];
            bs1v[jj * 4 + 1] = bi1[H_ + j] + bh1[H_ + j];
            bs1v[jj * 4 + 2] = bi1[2 * H_ + j];
            bs1v[jj * 4 + 3] = bh1[2 * H_ + j];
        }
    }

    const uint4* fWi0 = g_wA + FB0 + (size_t)jt * 3 * KT0 * 64 + lane;
    const uint4* fWh0 = g_wA + FB1 + (size_t)jt * 3 * KTH * 64 + lane;
    const uint4* fWi1 = g_wA + FB2 + (size_t)jt * 3 * KTH * 64 + lane;
    const uint4* fWh1 = g_wA + FB3 + (size_t)jt * 3 * KTH * 64 + lane;
    const unsigned boff = nsub * 128 + (lane >> 2) * 4 + (lane & 3);
    const int kgs0 = ks * 8  + ksub * 2;
    const int kgsH = ks * 32 + ksub * 8;

    float* pOwn0 = g_pL0 + cta * 4096;
    float* pOwn1 = g_pL1 + cta * 4096;
    const float* pPar0 = g_pL0 + (cta ^ 1) * 4096;
    const float* pPar1 = g_pL1 + (cta ^ 1) * 4096;

    unsigned gen = 0;
    grid_sync(++gen);

    for (int p = 0; p <= T_; ++p) {
        if (p < T_) {
            float aR[4][4] = {}, aZ[4][4] = {}, aNi[4][4] = {}, aNh[4][4] = {};
            mainloop2<KT0, 2, KTH, 8>(
                fWi0, g_xx + (size_t)p * 4096 + boff, kgs0,
                fWh0, g_h0x[(p + 1) & 1] + boff, kgsH,
                sbase, aR, aZ, aNi, aNh);
            REDUCE_PUBLISH(aR, aZ, aNi, aNh, pOwn0);
        }
        __syncthreads();
        if (tid == 0 && p < T_) { __threadfence(); g_fL0[cta] = p + 1; }
        if (p > 0) {
            float aR[4][4] = {}, aZ[4][4] = {}, aNi[4][4] = {}, aNh[4][4] = {};
            mainloop2<KTH, 8, KTH, 8>(
                fWi1, g_h0x[(p + 1) & 1] + boff, kgsH,
                fWh1, g_h1x[p & 1] + boff, kgsH,
                sbase, aR, aZ, aNi, aNh);
            REDUCE_PUBLISH(aR, aZ, aNi, aNh, pOwn1);
        }
        __syncthreads();
        if (tid == 0) {
            if (p > 0) { __threadfence(); g_fL1[cta] = p; }
            if (p < T_) while (g_fL0[cta ^ 1] < (unsigned)(p + 1)) { }
            if (p > 0)  while (g_fL1[cta ^ 1] < (unsigned)p) { }
            __threadfence();
        }
        __syncthreads();
        if (p < T_)
            gatepass(pOwn0, pPar0, bs0v, g_h0f[(p + 1) & 1], g_h0f[p & 1],
                     g_h0x[p & 1], jt, ks, tid);
        if (p > 0)
            gatepass(pOwn1, pPar1, bs1v, g_h1f[p & 1], g_h1f[(p + 1) & 1],
                     g_h1x[(p + 1) & 1], jt, ks, tid);
        grid_sync(++gen);
    }

    if (tid < 128) {
        const int o = cta * 2 + (tid >> 6);
        const int b = tid & 63;
        const float* w  = Wo + (size_t)o * H_;
        const float* hv = g_h1f[1] + (size_t)b * H_;
        float acc = 0.f;
#pragma unroll 4
        for (int k = 0; k < H_; k += 4) {
            float4 wv = *reinterpret_cast<const float4*>(w + k);
            float4 h4 = *reinterpret_cast<const float4*>(hv + k);
            acc += wv.x * h4.x + wv.y * h4.y + wv.z * h4.z + wv.w * h4.w;
        }
        out[(size_t)b * DOUT + o] = acc + bo[o];
    }

    __syncthreads();
    if (tid == 0) {
        unsigned old = atomicAdd(&g_done, 1u);
        if (old == NCTA - 1u) {
            for (int i = 0; i < NCTA; ++i) { g_fL0[i] = 0u; g_fL1[i] = 0u; }
            g_bar = 0u;
            g_done = 0u;
            __threadfence();
        }
    }
}

extern "C" void kernel_launch(void* const* d_in, const int* in_sizes, int n_in,
                              void* d_out, int out_size)
{
    cudaFuncSetAttribute(gru_tc4, cudaFuncAttributeMaxDynamicSharedMemorySize,
                         DYNSM);
    gru_tc4<<<NCTA, NT, DYNSM>>>(
        (const float*)d_in[0], (const float*)d_in[1], (const float*)d_in[2],
        (const float*)d_in[3], (const float*)d_in[4], (const float*)d_in[5],
        (const float*)d_in[6], (const float*)d_in[7], (const float*)d_in[8],
        (const float*)d_in[9], (const float*)d_in[10], (float*)d_out);
}